// round 8
// baseline (speedup 1.0000x reference)
#include <cuda_runtime.h>

// Neural 2D min-sum LDPC decoder, (3,6)-regular layered graph.
// One CTA per codeword, TWO CTAs co-resident per SM (TPB=512, 96KB smem each)
// so barrier stalls of one CTA are hidden by the other's issue slots.
// Edge state (3*8192 floats = 96KB) smem-resident for all T iterations.
// msg[l*NV + v]: v2c after var phase, c2v after check phase (in-place; per
// layer each variable belongs to exactly one check).
// Check c, layer l owns edges e = l*NV + 2c + {0,1} (edge_c = i>>1).
//
// Layout law (R5/R6 lesson): var phase strided scalar 4B (coalesced, 1 phase
// per warp request); vector/paired layouts double conflict phases.
// Register law: 2 CTAs/SM caps regs at 64/thread -> llr is re-read from GMEM
// (L2-resident) each var phase instead of living in registers.

#define NV 8192
#define MC 4096
#define NL 3
#define TPB 512
#define VPT (NV / TPB)    // 16 strided variables per thread
#define CPT (MC / TPB)    // 8 checks per thread (strided)
#define SMEM_BYTES (NL * NV * 4)

// Multiset 2-min min-sum core on sign-magnitude bits; exactly reproduces the
// reference min1/min2/argmin + sign-product semantics (incl. ties and zeros).
// (validated rel_err==0.0 in R5/R6/R7 benches)
__device__ __forceinline__ void minsum6(const unsigned u[6], float bt, unsigned res[6])
{
    unsigned a0 = u[0] & 0x7fffffffu, a1 = u[1] & 0x7fffffffu;
    unsigned a2 = u[2] & 0x7fffffffu, a3 = u[3] & 0x7fffffffu;
    unsigned a4 = u[4] & 0x7fffffffu, a5 = u[5] & 0x7fffffffu;
    unsigned xs = (u[0] ^ u[1]) ^ (u[2] ^ u[3]) ^ (u[4] ^ u[5]);

    // nonnegative float bits order as unsigned ints
    unsigned lo01 = min(a0, a1), hi01 = max(a0, a1);
    unsigned lo23 = min(a2, a3), hi23 = max(a2, a3);
    unsigned lo45 = min(a4, a5), hi45 = max(a4, a5);
    unsigned m1a  = min(lo01, lo23);
    unsigned m2a  = min(max(lo01, lo23), min(hi01, hi23));
    unsigned m1   = min(m1a, lo45);
    unsigned m2   = min(max(m1a, lo45), min(m2a, hi45));
    m2 = (m1 == 0u) ? 0u : m2;   // exact zero => sign product 0 => all c2v = 0

    unsigned b1 = __float_as_uint(bt * __uint_as_float(m1));
    unsigned b2 = __float_as_uint(bt * __uint_as_float(m2));

    unsigned as[6] = {a0, a1, a2, a3, a4, a5};
#pragma unroll
    for (int p = 0; p < 6; p++) {
        unsigned mag = (as[p] == m1) ? b2 : b1;          // ties => b1==b2
        res[p] = mag ^ ((xs ^ u[p]) & 0x80000000u);
    }
}

__global__ __launch_bounds__(TPB, 2)
void bp_kernel(const float* __restrict__ llr,
               const int*   __restrict__ edge_v,
               const float* __restrict__ beta,
               const float* __restrict__ alpha,
               float* __restrict__ out_f,
               int*   __restrict__ out_i,
               int B, int T, int mode)
{
    extern __shared__ float msg[];   // [NL*NV]

    const int tid = threadIdx.x;

    // Register-resident check->var table (graph fixed across codewords/iters).
    unsigned pk[CPT][NL];
#pragma unroll
    for (int k = 0; k < CPT; k++) {
        int c = tid + k * TPB;
#pragma unroll
        for (int l = 0; l < NL; l++) {
            unsigned v0 = (unsigned)edge_v[l * NV + 2 * c];
            unsigned v1 = (unsigned)edge_v[l * NV + 2 * c + 1];
            pk[k][l] = v0 | (v1 << 16);
        }
    }

    for (int cw = blockIdx.x; cw < B; cw += gridDim.x) {
        const float* llr_cw = llr + (size_t)cw * NV;

        // v2c init = llr at each edge (coalesced LDG + scalar STS).
#pragma unroll
        for (int k = 0; k < VPT; k++) {
            int v = tid + k * TPB;
            float x = __ldg(llr_cw + v);
            msg[v]          = x;
            msg[NV + v]     = x;
            msg[2 * NV + v] = x;
        }
        __syncthreads();

        for (int t = 0; t < T; t++) {
            float bt = __ldg(beta + t);
            float at = __ldg(alpha + t);

            // ---------- check phase: v2c -> c2v (in place) ----------
#pragma unroll 1
            for (int k = 0; k < CPT; k++) {
                int vi[6];
#pragma unroll
                for (int l = 0; l < NL; l++) {
                    vi[2 * l]     = (int)(pk[k][l] & 0xFFFFu);
                    vi[2 * l + 1] = (int)(pk[k][l] >> 16);
                }
                unsigned u[6];
#pragma unroll
                for (int p = 0; p < 6; p++)
                    u[p] = __float_as_uint(msg[(p >> 1) * NV + vi[p]]);  // random LDS.32

                unsigned r[6];
                minsum6(u, bt, r);
#pragma unroll
                for (int p = 0; p < 6; p++)
                    msg[(p >> 1) * NV + vi[p]] = __uint_as_float(r[p]); // random STS.32
            }
            __syncthreads();

            // ---------- variable phase: c2v -> v2c (skip after last iter) ----------
            if (t + 1 < T) {
#pragma unroll 1
                for (int k = 0; k < VPT; k++) {
                    int v = tid + k * TPB;           // coalesced, conflict-free
                    float base = __ldg(llr_cw + v);  // L2-resident reload (reg cap)
                    float c0 = msg[v];
                    float c1 = msg[NV + v];
                    float c2 = msg[2 * NV + v];
                    float sv = c0 + c1 + c2;
                    msg[v]          = base + at * (sv - c0);
                    msg[NV + v]     = base + at * (sv - c1);
                    msg[2 * NV + v] = base + at * (sv - c2);
                }
                __syncthreads();
            }
        }

        // ---------- posterior + hard decision ----------
#pragma unroll 1
        for (int k = 0; k < VPT; k++) {
            int v = tid + k * TPB;
            float post = __ldg(llr_cw + v) + (msg[v] + msg[NV + v] + msg[2 * NV + v]);
            size_t idx = (size_t)cw * NV + v;
            if (mode) {
                // out = [decoded_bits (as f32 0/1) | posterior], each [B,N]
                out_f[idx] = (post < 0.0f) ? 1.0f : 0.0f;
                out_f[(size_t)B * NV + idx] = post;
            } else {
                out_i[idx] = (post < 0.0f) ? 1 : 0;
            }
        }
        __syncthreads();   // protect msg before next codeword reuses it
    }
}

extern "C" void kernel_launch(void* const* d_in, const int* in_sizes, int n_in,
                              void* d_out, int out_size) {
    // metadata order: llr [B,N] f32, edge_v [E] i32, edge_c [E] i32 (implicit),
    // beta [T] f32, alpha [T] f32
    const float* llr    = (const float*)d_in[0];
    const int*   edge_v = (const int*)  d_in[1];
    const float* beta   = (const float*)d_in[3];
    const float* alpha  = (const float*)d_in[4];

    int B = in_sizes[0] / NV;
    int T = in_sizes[3];
    int mode = (out_size >= 2 * B * NV) ? 1 : 0;

    cudaFuncSetAttribute((const void*)bp_kernel,
                         cudaFuncAttributeMaxDynamicSharedMemorySize, SMEM_BYTES);
    bp_kernel<<<B, TPB, SMEM_BYTES>>>(llr, edge_v, beta, alpha,
                                      (float*)d_out, (int*)d_out, B, T, mode);
}

// round 10
// speedup vs baseline: 1.2083x; 1.2083x over previous
#include <cuda_runtime.h>

// Neural 2D min-sum LDPC decoder, (3,6)-regular layered graph.
// One CTA per codeword (TPB=1024, 96KB smem, 1 CTA/SM) — R7 configuration,
// which measurement shows beats both float2-pairing (R6) and 2-CTA/SM (R8).
// Edge state msg[l*NV + v] smem-resident for all T iterations; in-place
// check/variable updates (per layer each variable is in exactly one check).
// Check c, layer l owns edges e = l*NV + 2c + {0,1} (edge_c = i>>1).
//
// R9 change (resubmitted after broker failure): software-pipelined check phase.
// Next check's 6 random LDS are issued BEFORE the current check's STS
// (disjointness provable: different checks own different variables per layer),
// hiding LDS latency + bank-conflict serialization under the minsum compute.
// Var phase batches 2 strides for doubled loads-in-flight.

#define NV 8192
#define MC 4096
#define NL 3
#define TPB 1024
#define VPT (NV / TPB)    // 8 strided variables per thread
#define CPT (MC / TPB)    // 4 checks per thread (strided)
#define SMEM_BYTES (NL * NV * 4)

// Multiset 2-min min-sum core on sign-magnitude bits; exactly reproduces the
// reference min1/min2/argmin + sign-product semantics (incl. ties and zeros).
// (validated rel_err==0.0 in R5-R8 benches)
__device__ __forceinline__ void minsum6(const unsigned u[6], float bt, unsigned res[6])
{
    unsigned a0 = u[0] & 0x7fffffffu, a1 = u[1] & 0x7fffffffu;
    unsigned a2 = u[2] & 0x7fffffffu, a3 = u[3] & 0x7fffffffu;
    unsigned a4 = u[4] & 0x7fffffffu, a5 = u[5] & 0x7fffffffu;
    unsigned xs = (u[0] ^ u[1]) ^ (u[2] ^ u[3]) ^ (u[4] ^ u[5]);

    // nonnegative float bits order as unsigned ints
    unsigned lo01 = min(a0, a1), hi01 = max(a0, a1);
    unsigned lo23 = min(a2, a3), hi23 = max(a2, a3);
    unsigned lo45 = min(a4, a5), hi45 = max(a4, a5);
    unsigned m1a  = min(lo01, lo23);
    unsigned m2a  = min(max(lo01, lo23), min(hi01, hi23));
    unsigned m1   = min(m1a, lo45);
    unsigned m2   = min(max(m1a, lo45), min(m2a, hi45));
    m2 = (m1 == 0u) ? 0u : m2;   // exact zero => sign product 0 => all c2v = 0

    unsigned b1 = __float_as_uint(bt * __uint_as_float(m1));
    unsigned b2 = __float_as_uint(bt * __uint_as_float(m2));

    unsigned as[6] = {a0, a1, a2, a3, a4, a5};
#pragma unroll
    for (int p = 0; p < 6; p++) {
        unsigned mag = (as[p] == m1) ? b2 : b1;          // ties => b1==b2
        res[p] = mag ^ ((xs ^ u[p]) & 0x80000000u);
    }
}

__global__ __launch_bounds__(TPB, 1)
void bp_kernel(const float* __restrict__ llr,
               const int*   __restrict__ edge_v,
               const float* __restrict__ beta,
               const float* __restrict__ alpha,
               float* __restrict__ out_f,
               int*   __restrict__ out_i,
               int B, int T, int mode)
{
    extern __shared__ float msg[];   // [NL*NV]

    const int tid = threadIdx.x;

    // Register-resident check->var table (graph fixed across codewords/iters).
    unsigned pk[CPT][NL];
#pragma unroll
    for (int k = 0; k < CPT; k++) {
        int c = tid + k * TPB;
#pragma unroll
        for (int l = 0; l < NL; l++) {
            unsigned v0 = (unsigned)edge_v[l * NV + 2 * c];
            unsigned v1 = (unsigned)edge_v[l * NV + 2 * c + 1];
            pk[k][l] = v0 | (v1 << 16);
        }
    }

    for (int cw = blockIdx.x; cw < B; cw += gridDim.x) {
        // Channel LLRs: strided, coalesced, register-resident for the codeword.
        float llrv[VPT];
#pragma unroll
        for (int k = 0; k < VPT; k++)
            llrv[k] = llr[(size_t)cw * NV + tid + k * TPB];

        // v2c init = llr at each edge (coalesced scalar stores).
#pragma unroll
        for (int l = 0; l < NL; l++)
#pragma unroll
            for (int k = 0; k < VPT; k++)
                msg[l * NV + tid + k * TPB] = llrv[k];
        __syncthreads();

        for (int t = 0; t < T; t++) {
            float bt = __ldg(beta + t);
            float at = __ldg(alpha + t);

            // ---------- check phase: v2c -> c2v, software-pipelined ----------
            unsigned ucur[6], unxt[6];
#pragma unroll
            for (int l = 0; l < NL; l++) {
                ucur[2 * l]     = __float_as_uint(msg[l * NV + (int)(pk[0][l] & 0xFFFFu)]);
                ucur[2 * l + 1] = __float_as_uint(msg[l * NV + (int)(pk[0][l] >> 16)]);
            }
#pragma unroll
            for (int k = 0; k < CPT; k++) {
                // Prefetch next check's messages BEFORE storing this check's:
                // no alias possible (checks own disjoint variables per layer).
                if (k + 1 < CPT) {
#pragma unroll
                    for (int l = 0; l < NL; l++) {
                        unxt[2 * l]     = __float_as_uint(msg[l * NV + (int)(pk[k + 1][l] & 0xFFFFu)]);
                        unxt[2 * l + 1] = __float_as_uint(msg[l * NV + (int)(pk[k + 1][l] >> 16)]);
                    }
                }
                unsigned r[6];
                minsum6(ucur, bt, r);     // overlaps with unxt loads in flight
#pragma unroll
                for (int l = 0; l < NL; l++) {
                    msg[l * NV + (int)(pk[k][l] & 0xFFFFu)] = __uint_as_float(r[2 * l]);
                    msg[l * NV + (int)(pk[k][l] >> 16)]     = __uint_as_float(r[2 * l + 1]);
                }
                if (k + 1 < CPT) {
#pragma unroll
                    for (int p = 0; p < 6; p++) ucur[p] = unxt[p];
                }
            }
            __syncthreads();

            // ---------- variable phase: c2v -> v2c, 2-stride batches ----------
            if (t + 1 < T) {
#pragma unroll
                for (int k = 0; k < VPT; k += 2) {
                    int va = tid + k * TPB;          // coalesced, conflict-free
                    int vb = tid + (k + 1) * TPB;
                    float a0 = msg[va], a1 = msg[NV + va], a2 = msg[2 * NV + va];
                    float b0 = msg[vb], b1 = msg[NV + vb], b2 = msg[2 * NV + vb];
                    float sa = a0 + a1 + a2, ba = llrv[k];
                    float sb = b0 + b1 + b2, bb = llrv[k + 1];
                    msg[va]          = ba + at * (sa - a0);
                    msg[NV + va]     = ba + at * (sa - a1);
                    msg[2 * NV + va] = ba + at * (sa - a2);
                    msg[vb]          = bb + at * (sb - b0);
                    msg[NV + vb]     = bb + at * (sb - b1);
                    msg[2 * NV + vb] = bb + at * (sb - b2);
                }
                __syncthreads();
            }
        }

        // ---------- posterior + hard decision ----------
#pragma unroll
        for (int k = 0; k < VPT; k++) {
            int v = tid + k * TPB;
            float post = llrv[k] + (msg[v] + msg[NV + v] + msg[2 * NV + v]);
            size_t idx = (size_t)cw * NV + v;
            if (mode) {
                // out = [decoded_bits (as f32 0/1) | posterior], each [B,N]
                out_f[idx] = (post < 0.0f) ? 1.0f : 0.0f;
                out_f[(size_t)B * NV + idx] = post;
            } else {
                out_i[idx] = (post < 0.0f) ? 1 : 0;
            }
        }
        __syncthreads();   // protect msg before next codeword reuses it
    }
}

extern "C" void kernel_launch(void* const* d_in, const int* in_sizes, int n_in,
                              void* d_out, int out_size) {
    // metadata order: llr [B,N] f32, edge_v [E] i32, edge_c [E] i32 (implicit),
    // beta [T] f32, alpha [T] f32
    const float* llr    = (const float*)d_in[0];
    const int*   edge_v = (const int*)  d_in[1];
    const float* beta   = (const float*)d_in[3];
    const float* alpha  = (const float*)d_in[4];

    int B = in_sizes[0] / NV;
    int T = in_sizes[3];
    int mode = (out_size >= 2 * B * NV) ? 1 : 0;

    cudaFuncSetAttribute((const void*)bp_kernel,
                         cudaFuncAttributeMaxDynamicSharedMemorySize, SMEM_BYTES);
    bp_kernel<<<B, TPB, SMEM_BYTES>>>(llr, edge_v, beta, alpha,
                                      (float*)d_out, (int*)d_out, B, T, mode);
}